// round 10
// baseline (speedup 1.0000x reference)
#include <cuda_runtime.h>
#include <cuda_fp16.h>

// ---------------- problem constants ----------------
#define TT    1200
#define NF    10
#define KK    17
#define NTP   76
#define NTPG  19
#define FEAT  760
#define NSTR  240            // 5-wide strips per row
#define THREADS 256
#define BROW  66             // B row stride in halfs (conflict-free, keeps 4B align)
#define Y2W   56             // Y2 row stride in floats

// GEMM: D[m][n] = sum_k A[m][k] B[n][k],  m=strip(240), n=5f+j (50, pad 56), K=64
//   A cols: [0,21): x_hi[5m-8+k]  [21,42): x_lo[...]  [42,63): x_hi again  63: 0
//   B cols: [0,21): w_hi[f][k-j]  [21,42): w_hi       [42,63): w_lo[f][..] 63: 0
//   => D = x*w  (error ~2^-24, fp32 accum)

// ---------------- smem offsets (bytes) ----------------
#define OFF_OUT 0
#define OFF_CB  16                    // 10 floats bias
#define OFF_XH  64                    // 1216 halfs  (x hi, 8-halo)
#define OFF_XL  2496                  // 1216 halfs  (x lo)
#define OFF_B   4928                  // 56 x 66 halfs
#define OFF_S   12320                 // 10 x 240 floats (strip sums)
#define OFF_Y2  21920                 // 240 x 56 floats (y^2)
#define SMEM_TOTAL 75680

__device__ __forceinline__ void mma16816(float c[4], const unsigned a[4], const unsigned b[2]) {
    asm volatile(
        "mma.sync.aligned.m16n8k16.row.col.f32.f16.f16.f32 "
        "{%0,%1,%2,%3}, {%4,%5,%6,%7}, {%8,%9}, {%0,%1,%2,%3};"
        : "+f"(c[0]), "+f"(c[1]), "+f"(c[2]), "+f"(c[3])
        : "r"(a[0]), "r"(a[1]), "r"(a[2]), "r"(a[3]), "r"(b[0]), "r"(b[1]));
}

// A element fetch: arrays indexed so arr[i] = value at x(t = i-8)
__device__ __forceinline__ unsigned short a_h(const unsigned short* xh,
                                              const unsigned short* xl,
                                              int i5, int k) {
    unsigned short v = 0;
    if (k < 21)      v = xh[i5 + k];
    else if (k < 42) v = xl[i5 + k - 21];
    else if (k < 63) v = xh[i5 + k - 42];
    return v;
}
__device__ __forceinline__ unsigned packh(unsigned short lo, unsigned short hi) {
    return ((unsigned)hi << 16) | (unsigned)lo;
}

__global__ __launch_bounds__(THREADS) void scorer_hmma_kernel(
    const float* __restrict__ x,       // (B,1,M,T) rows of 1200
    const float* __restrict__ conv_w,  // (NF,KK)
    const float* __restrict__ conv_b,  // (NF)
    const float* __restrict__ lin_w,   // (M,FEAT)
    const float* __restrict__ lin_b,   // (M)
    float* __restrict__ out)           // (B,M,1)
{
    extern __shared__ char smem[];
    float*          s_out = (float*)(smem + OFF_OUT);
    float*          s_cb  = (float*)(smem + OFF_CB);
    unsigned short* s_xh  = (unsigned short*)(smem + OFF_XH);
    unsigned short* s_xl  = (unsigned short*)(smem + OFF_XL);
    unsigned short* s_B   = (unsigned short*)(smem + OFF_B);
    float*          s_S   = (float*)(smem + OFF_S);
    float*          s_Y2  = (float*)(smem + OFF_Y2);

    const int tid  = threadIdx.x;
    const int wid  = tid >> 5;
    const int lane = tid & 31;
    const int r    = lane >> 2;        // fragment group id
    const int q    = lane & 3;         // thread-in-group
    const int row  = blockIdx.x;       // b*64 + m
    const int m0   = row & 63;

    // ---- Phase 0: stage x hi/lo, B, bias ----
    {
        const float* xr = x + (size_t)row * TT;
        for (int i = tid; i < TT + 16; i += THREADS) {
            const int t = i - 8;
            const float v = (t >= 0 && t < TT) ? xr[t] : 0.f;
            const __half h = __float2half_rn(v);
            const __half l = __float2half_rn(v - __half2float(h));
            s_xh[i] = __half_as_ushort(h);
            s_xl[i] = __half_as_ushort(l);
        }
    }
    for (int idx = tid; idx < 56 * 64; idx += THREADS) {
        const int n = idx >> 6;
        const int k = idx & 63;
        unsigned short v = 0;
        if (n < 50 && k < 63) {
            const int f = n / 5, j = n - 5 * f;
            int kk; bool lo;
            if      (k < 21) { kk = k - j;      lo = false; }
            else if (k < 42) { kk = k - 21 - j; lo = false; }
            else             { kk = k - 42 - j; lo = true;  }
            if (kk >= 0 && kk < KK) {
                const float w  = conv_w[f * KK + kk];
                const __half h = __float2half_rn(w);
                if (!lo) v = __half_as_ushort(h);
                else     v = __half_as_ushort(__float2half_rn(w - __half2float(h)));
            }
        }
        s_B[n * BROW + k] = v;
    }
    if (tid < NF) s_cb[tid] = conv_b[tid];
    if (tid == 0) s_out[0] = 0.f;
    __syncthreads();

    // ---- Phase 1: HMMA GEMM + fragment epilogue -> Y2 ----
    #pragma unroll
    for (int mi = 0; mi < 2; ++mi) {
        const int mt = wid + 8 * mi;          // m-tile 0..14
        if (mt < 15) {
            float acc[7][4];
            #pragma unroll
            for (int nt = 0; nt < 7; ++nt)
                #pragma unroll
                for (int c = 0; c < 4; ++c) acc[nt][c] = 0.f;

            const int mA  = mt * 16 + r;      // rows for c0/c1
            const int i5a = 5 * mA;
            const int i5b = 5 * (mA + 8);     // rows for c2/c3

            #pragma unroll
            for (int ks = 0; ks < 4; ++ks) {
                const int kb = 16 * ks + 2 * q;
                unsigned a[4];
                a[0] = packh(a_h(s_xh, s_xl, i5a, kb),     a_h(s_xh, s_xl, i5a, kb + 1));
                a[1] = packh(a_h(s_xh, s_xl, i5b, kb),     a_h(s_xh, s_xl, i5b, kb + 1));
                a[2] = packh(a_h(s_xh, s_xl, i5a, kb + 8), a_h(s_xh, s_xl, i5a, kb + 9));
                a[3] = packh(a_h(s_xh, s_xl, i5b, kb + 8), a_h(s_xh, s_xl, i5b, kb + 9));
                #pragma unroll
                for (int nt = 0; nt < 7; ++nt) {
                    const unsigned short* brow = s_B + (8 * nt + r) * BROW + kb;
                    unsigned b[2];
                    b[0] = *(const unsigned*)(brow);       // halfs kb, kb+1
                    b[1] = *(const unsigned*)(brow + 8);   // halfs kb+8, kb+9
                    mma16816(acc[nt], a, b);
                }
            }
            // epilogue: +bias, square, store Y2
            #pragma unroll
            for (int nt = 0; nt < 7; ++nt) {
                const int n0 = 8 * nt + 2 * q;
                if (n0 < 50) {
                    const float b0 = s_cb[n0 / 5];
                    const float b1 = s_cb[(n0 + 1) / 5];
                    const float y0 = acc[nt][0] + b0, y1 = acc[nt][1] + b1;
                    const float y2 = acc[nt][2] + b0, y3 = acc[nt][3] + b1;
                    float2 v0; v0.x = y0 * y0; v0.y = y1 * y1;
                    float2 v1; v1.x = y2 * y2; v1.y = y3 * y3;
                    *(float2*)&s_Y2[(size_t)mA * Y2W + n0]       = v0;
                    *(float2*)&s_Y2[(size_t)(mA + 8) * Y2W + n0] = v1;
                }
            }
        }
    }
    __syncthreads();

    // ---- Phase 2: strip sums S[f][strip] = sum_j Y2[strip][5f+j] ----
    for (int idx = tid; idx < NF * NSTR; idx += THREADS) {
        const int f = idx / NSTR;
        const int s = idx - f * NSTR;
        const float* yp = &s_Y2[(size_t)s * Y2W + 5 * f];
        s_S[f * NSTR + s] = ((yp[0] + yp[1]) + (yp[2] + yp[3])) + yp[4];
    }
    __syncthreads();

    // ---- Phase 3: sliding pool (15 strips, hop 3) -> log -> dot ----
    float part = 0.f;
    for (int task = tid; task < NF * NTPG; task += THREADS) {   // 190 tasks
        const int f = task / NTPG;
        const int g = task - f * NTPG;        // covers tp = 4g .. 4g+3
        const float* Sp = &s_S[f * NSTR + 12 * g];
        float sv[24];
        #pragma unroll
        for (int j = 0; j < 24; ++j) sv[j] = Sp[j];
        float run = 0.f;
        #pragma unroll
        for (int j = 0; j < 15; ++j) run += sv[j];
        const float4 lw = *(const float4*)&lin_w[(size_t)m0 * FEAT + f * NTP + 4 * g];
        #pragma unroll
        for (int qq = 0; qq < 4; ++qq) {
            const float p = fmaxf(run * (1.0f / 75.0f), 1e-10f);
            const float v = __logf(p);
            const float w = (qq == 0) ? lw.x : (qq == 1) ? lw.y : (qq == 2) ? lw.z : lw.w;
            part = fmaf(v, w, part);
            if (qq < 3) {
                run += (sv[15 + 3*qq] + sv[16 + 3*qq] + sv[17 + 3*qq])
                     - (sv[3*qq] + sv[1 + 3*qq] + sv[2 + 3*qq]);
            }
        }
    }
    #pragma unroll
    for (int off = 16; off > 0; off >>= 1)
        part += __shfl_down_sync(0xffffffffu, part, off);
    if (lane == 0) atomicAdd(&s_out[0], part);
    __syncthreads();

    if (tid == 0) out[row] = s_out[0] + lin_b[m0];
}

extern "C" void kernel_launch(void* const* d_in, const int* in_sizes, int n_in,
                              void* d_out, int out_size) {
    const float* x      = (const float*)d_in[0];
    const float* conv_w = (const float*)d_in[1];
    const float* conv_b = (const float*)d_in[2];
    const float* lin_w  = (const float*)d_in[3];
    const float* lin_b  = (const float*)d_in[4];
    float* out = (float*)d_out;

    cudaFuncSetAttribute(scorer_hmma_kernel,
                         cudaFuncAttributeMaxDynamicSharedMemorySize, SMEM_TOTAL);
    scorer_hmma_kernel<<<256 * 64, THREADS, SMEM_TOTAL>>>(x, conv_w, conv_b, lin_w, lin_b, out);
}